// round 9
// baseline (speedup 1.0000x reference)
#include <cuda_runtime.h>
#include <cuda_fp16.h>
#include <cstdint>

#define Q_TOTAL 65536
#define CPROT   64
#define DDIM    512
#define QT      128
#define KC      64
#define NCH     (DDIM / KC)         // 8
#define AST     144                 // A smem row stride (64 halves + pad)
#define BST     1040                // B smem row stride (512 halves + pad)
#define ABUF    (QT * AST)          // 18432 per A buffer

// ---- dynamic smem layout (bytes) ----
#define OFF_B    0
#define OFF_A    (OFF_B + CPROT * BST)      // 66560
#define OFF_SUMQ (OFF_A + 2 * ABUF)         // 103424 (128 floats)
#define OFF_SUMP (OFF_SUMQ + 512)           // 103936 (64 floats)
#define OFF_CMB  (OFF_SUMP + 256)           // 104192 (6*128 floats)
#define SMEM_TOTAL (OFF_CMB + 3072)         // 107264

#define NPART 2048

// -------- device scratch --------
__device__ float g_sump[2][CPROT];
__device__ uint4 g_ph4[2][4096];    // proto fp16: [mod][row*64 + unit], 8 fp16/unit
__device__ float g_c  [2][Q_TOTAL];
__device__ float g_h  [2][Q_TOTAL];
__device__ float g_S  [2][Q_TOTAL];
__device__ float g_klfr[Q_TOTAL];
__device__ float g_klrf[Q_TOTAL];
__device__ float g_part[5][NPART];

// -------- helpers --------
__device__ __forceinline__ uint32_t smem_u32(const void* p) {
    uint32_t a;
    asm("{ .reg .u64 t; cvta.to.shared.u64 t, %1; cvt.u32.u64 %0, t; }"
        : "=r"(a) : "l"(p));
    return a;
}

#define LDM4(r, a) \
    asm volatile("ldmatrix.sync.aligned.m8n8.x4.shared.b16 {%0,%1,%2,%3}, [%4];" \
        : "=r"((r)[0]), "=r"((r)[1]), "=r"((r)[2]), "=r"((r)[3]) : "r"(a))

__device__ __forceinline__ void mma16816(float* d, const uint32_t* a, const uint32_t* b) {
    asm volatile(
        "mma.sync.aligned.m16n8k16.row.col.f32.f16.f16.f32 "
        "{%0,%1,%2,%3}, {%4,%5,%6,%7}, {%8,%9}, {%0,%1,%2,%3};"
        : "+f"(d[0]), "+f"(d[1]), "+f"(d[2]), "+f"(d[3])
        : "r"(a[0]), "r"(a[1]), "r"(a[2]), "r"(a[3]), "r"(b[0]), "r"(b[1]));
}

__device__ __forceinline__ uint32_t h2pack(float x, float y) {
    __half2 h = __float22half2_rn(make_float2(x, y));
    return *reinterpret_cast<uint32_t*>(&h);
}

__device__ __forceinline__ float fast_sqrt(float x) {
    float xc = fmaxf(x, 1e-12f);
    return xc * rsqrtf(xc);
}

// -------- kernel 1: proto norms + proto fp16 precompute --------
__global__ void prep_kernel(const float* __restrict__ ctx_r,
                            const float* __restrict__ ctx_f) {
    const int mod = blockIdx.x;
    const float* ctx = mod ? ctx_f : ctx_r;
    const int tid = threadIdx.x;
    const int warp = tid >> 5, lane = tid & 31;

    for (int p = warp; p < CPROT; p += 8) {
        float s = 0.f;
        const float* row = ctx + (size_t)p * DDIM;
        for (int k = lane; k < DDIM; k += 32) { float v = row[k]; s += v * v; }
        #pragma unroll
        for (int o = 16; o; o >>= 1) s += __shfl_xor_sync(0xffffffffu, s, o);
        if (lane == 0) g_sump[mod][p] = s;
    }
    for (int i = tid; i < 4096; i += 256) {
        const int row = i >> 6, u8 = i & 63;
        const float4 v0 = *(const float4*)(ctx + (size_t)row * DDIM + u8 * 8);
        const float4 v1 = *(const float4*)(ctx + (size_t)row * DDIM + u8 * 8 + 4);
        g_ph4[mod][i] = make_uint4(h2pack(v0.x, v0.y), h2pack(v0.z, v0.w),
                                   h2pack(v1.x, v1.y), h2pack(v1.z, v1.w));
    }
}

// -------- kernel 2: B-resident, double-buffered-A fp16 mma posterior --------
extern __shared__ char sm_dyn[];

__global__ void __launch_bounds__(256, 2)
posterior_mma(const float* __restrict__ tgt_r, const float* __restrict__ tgt_f,
              float* __restrict__ out) {
    char* sm = sm_dyn;
    const int mod = blockIdx.y;
    const float* __restrict__ tgt = mod ? tgt_f : tgt_r;
    float* out_p = out + 2 + (mod ? (size_t)0 : (size_t)Q_TOTAL * CPROT);

    const int tid = threadIdx.x;
    const int l   = tid & 31;
    const int w   = tid >> 5;
    const int wq  = w & 3;          // 4 q-groups of 32 rows
    const int wp  = w >> 2;         // 2 p-groups of 32 cols
    const size_t qbase = (size_t)blockIdx.x * QT;

    const uint32_t sb = smem_u32(sm);
    float* sumq = (float*)(sm + OFF_SUMQ);
    float* sump = (float*)(sm + OFF_SUMP);
    float* cmb  = (float*)(sm + OFF_CMB);

    if (tid < CPROT) sump[tid] = g_sump[mod][tid];

    // ---- load B (all K) into resident smem: 4096 uint4 ----
    #pragma unroll
    for (int j = 0; j < 16; ++j) {
        const int i = j * 256 + tid;
        *(uint4*)(sm + OFF_B + (i >> 6) * BST + (i & 63) * 16) = g_ph4[mod][i];
    }

    float d[2][4][4];
    #pragma unroll
    for (int mt = 0; mt < 2; ++mt)
        #pragma unroll
        for (int n = 0; n < 4; ++n)
            #pragma unroll
            for (int u = 0; u < 4; ++u) d[mt][n][u] = 0.f;

    float qn[4] = {0.f, 0.f, 0.f, 0.f};

    // ldmatrix lane offsets
    const uint32_t aoff = (uint32_t)((l & 15) * AST + (l >> 4) * 16);
    const uint32_t boff = (uint32_t)(((l & 7) + ((l >> 4) << 3)) * BST + (((l >> 3) & 1) * 16));
    uint32_t aHB[2], bHB[2];
    #pragma unroll
    for (int mt = 0; mt < 2; ++mt)
        aHB[mt] = sb + OFF_A + (32 * wq + 16 * mt) * AST + aoff;
    #pragma unroll
    for (int np = 0; np < 2; ++np)
        bHB[np] = sb + OFF_B + (32 * wp + 16 * np) * BST + boff;

    // staging coords: thread owns rows 32j + srow (j=0..3), cols scol..scol+7
    const int srow = (tid >> 3) & 31;
    const int scol = (tid & 7) * 8;
    const float* abase = tgt + (qbase + srow) * DDIM + scol;

    float4 va[8];
    #pragma unroll
    for (int j = 0; j < 4; ++j) {
        const float* p = abase + (size_t)32 * j * DDIM;          // chunk 0
        va[2 * j]     = __ldcs((const float4*)p);
        va[2 * j + 1] = __ldcs((const float4*)(p + 4));
    }
    // store chunk 0 -> buf 0
    #pragma unroll
    for (int j = 0; j < 4; ++j) {
        uint4 u = make_uint4(h2pack(va[2*j].x, va[2*j].y), h2pack(va[2*j].z, va[2*j].w),
                             h2pack(va[2*j+1].x, va[2*j+1].y), h2pack(va[2*j+1].z, va[2*j+1].w));
        *(uint4*)(sm + OFF_A + (32 * j + srow) * AST + (tid & 7) * 16) = u;
        qn[j] += va[2*j].x*va[2*j].x + va[2*j].y*va[2*j].y + va[2*j].z*va[2*j].z + va[2*j].w*va[2*j].w
               + va[2*j+1].x*va[2*j+1].x + va[2*j+1].y*va[2*j+1].y + va[2*j+1].z*va[2*j+1].z + va[2*j+1].w*va[2*j+1].w;
    }
    // prefetch chunk 1
    #pragma unroll
    for (int j = 0; j < 4; ++j) {
        const float* p = abase + (size_t)32 * j * DDIM + KC;
        va[2 * j]     = __ldcs((const float4*)p);
        va[2 * j + 1] = __ldcs((const float4*)(p + 4));
    }
    __syncthreads();

    for (int c = 0; c < NCH; ++c) {
        const int cur = c & 1;
        if (c + 1 < NCH) {
            const int nxt = (c + 1) & 1;
            #pragma unroll
            for (int j = 0; j < 4; ++j) {
                uint4 u = make_uint4(h2pack(va[2*j].x, va[2*j].y), h2pack(va[2*j].z, va[2*j].w),
                                     h2pack(va[2*j+1].x, va[2*j+1].y), h2pack(va[2*j+1].z, va[2*j+1].w));
                *(uint4*)(sm + OFF_A + nxt * ABUF + (32 * j + srow) * AST + (tid & 7) * 16) = u;
                qn[j] += va[2*j].x*va[2*j].x + va[2*j].y*va[2*j].y + va[2*j].z*va[2*j].z + va[2*j].w*va[2*j].w
                       + va[2*j+1].x*va[2*j+1].x + va[2*j+1].y*va[2*j+1].y + va[2*j+1].z*va[2*j+1].z + va[2*j+1].w*va[2*j+1].w;
            }
            if (c + 2 < NCH) {
                #pragma unroll
                for (int j = 0; j < 4; ++j) {
                    const float* p = abase + (size_t)32 * j * DDIM + (c + 2) * KC;
                    va[2 * j]     = __ldcs((const float4*)p);
                    va[2 * j + 1] = __ldcs((const float4*)(p + 4));
                }
            }
        }
        // ---- MMA on buf[cur], B at chunk offset ----
        #pragma unroll
        for (int ks = 0; ks < 4; ++ks) {
            const uint32_t koA = cur * ABUF + ks * 32;
            const uint32_t koB = c * 128 + ks * 32;
            uint32_t ah[2][4], bh[2][4];
            #pragma unroll
            for (int mt = 0; mt < 2; ++mt) LDM4(ah[mt], aHB[mt] + koA);
            #pragma unroll
            for (int np = 0; np < 2; ++np) LDM4(bh[np], bHB[np] + koB);
            #pragma unroll
            for (int mt = 0; mt < 2; ++mt)
                #pragma unroll
                for (int n = 0; n < 4; ++n)
                    mma16816(d[mt][n], ah[mt], &bh[n >> 1][(n & 1) * 2]);
        }
        __syncthreads();
    }

    // ---- |q|^2 reduce: 8 lanes (l&7) share row 32j + srow ----
    #pragma unroll
    for (int j = 0; j < 4; ++j) {
        float s = qn[j];
        s += __shfl_xor_sync(0xffffffffu, s, 1);
        s += __shfl_xor_sync(0xffffffffu, s, 2);
        s += __shfl_xor_sync(0xffffffffu, s, 4);
        if ((l & 7) == 0) sumq[32 * j + srow] = s;
    }
    __syncthreads();

    // ---- epilogue pass 1: per-warp 32-col partials ----
    const int qr    = l >> 2;
    const int cbase = (l & 3) * 2;
    float sp[4][2];
    #pragma unroll
    for (int n = 0; n < 4; ++n) {
        sp[n][0] = sump[32 * wp + 8 * n + cbase];
        sp[n][1] = sump[32 * wp + 8 * n + cbase + 1];
    }

    #pragma unroll
    for (int mt = 0; mt < 2; ++mt)
        #pragma unroll
        for (int h = 0; h < 2; ++h) {
            const int r = 32 * wq + 16 * mt + 8 * h + qr;
            const float sq = sumq[r];
            float S = 0.f, T = 0.f, emax = 0.f;
            #pragma unroll
            for (int n = 0; n < 4; ++n) {
                float dist0 = fast_sqrt(sq - 2.f * d[mt][n][2 * h]     + sp[n][0]);
                float dist1 = fast_sqrt(sq - 2.f * d[mt][n][2 * h + 1] + sp[n][1]);
                float e0 = __expf(-dist0), e1 = __expf(-dist1);
                d[mt][n][2 * h]     = e0;
                d[mt][n][2 * h + 1] = e1;
                S += e0 + e1;
                T += e0 * dist0 + e1 * dist1;
                emax = fmaxf(emax, fmaxf(e0, e1));
            }
            #pragma unroll
            for (int o = 1; o < 4; o <<= 1) {
                S += __shfl_xor_sync(0xffffffffu, S, o);
                T += __shfl_xor_sync(0xffffffffu, T, o);
                emax = fmaxf(emax, __shfl_xor_sync(0xffffffffu, emax, o));
            }
            if ((l & 3) == 0) {
                cmb[wp * 128 + r]       = S;
                cmb[256 + wp * 128 + r] = T;
                cmb[512 + wp * 128 + r] = emax;
            }
        }
    __syncthreads();

    // ---- epilogue pass 2: combine col-groups, write ----
    #pragma unroll
    for (int mt = 0; mt < 2; ++mt)
        #pragma unroll
        for (int h = 0; h < 2; ++h) {
            const int r = 32 * wq + 16 * mt + 8 * h + qr;
            const float S = cmb[r] + cmb[128 + r];
            const float T = cmb[256 + r] + cmb[384 + r];
            const float M = fmaxf(cmb[512 + r], cmb[640 + r]);
            const float invS = 1.f / S;
            const size_t qg = qbase + r;
            float* orow = &out_p[qg * CPROT + 32 * wp];
            #pragma unroll
            for (int n = 0; n < 4; ++n)
                *(float2*)&orow[8 * n + cbase] =
                    make_float2(d[mt][n][2 * h] * invS, d[mt][n][2 * h + 1] * invS);
            if (wp == 0 && (l & 3) == 0) {
                g_c[mod][qg] = M * invS;
                g_S[mod][qg] = S;
                g_h[mod][qg] = __logf(S) + T * invS;
            }
        }
}

// -------- kernel 3: AMI fuse + per-query KL + block partials --------
__global__ void __launch_bounds__(1024)
fuse_kernel(float* __restrict__ out) {
    __shared__ float sm5[5][32];
    const int warp = threadIdx.x >> 5, lane = threadIdx.x & 31;
    const size_t q = (size_t)blockIdx.x * 32 + warp;
    const float* p_f = out + 2;
    const float* p_r = out + 2 + (size_t)Q_TOTAL * CPROT;
    float* post      = out + 2 + 2 * (size_t)Q_TOTAL * CPROT;

    float2 pf = *(const float2*)&p_f[q * CPROT + 2 * lane];
    float2 pr = *(const float2*)&p_r[q * CPROT + 2 * lane];
    float cr = g_c[0][q], cf = g_c[1][q];
    float Sr = g_S[0][q], Sf = g_S[1][q];
    float hr = g_h[0][q], hf = g_h[1][q];

    float klfr = pf.x * (__logf(pf.x) - pr.x) + pf.y * (__logf(pf.y) - pr.y);
    float klrf = pr.x * (__logf(pr.x) - pf.x) + pr.y * (__logf(pr.y) - pf.y);

    float inv = 1.f / (cr + cf);
    float a = cr * inv * Sr;
    float b = cf * inv * Sf;
    float fx = a * pr.x + b * pf.x;
    float fy = a * pr.y + b * pf.y;
    float fs = fx + fy;

    #pragma unroll
    for (int o = 1; o < 32; o <<= 1) {
        klfr += __shfl_xor_sync(0xffffffffu, klfr, o);
        klrf += __shfl_xor_sync(0xffffffffu, klrf, o);
        fs   += __shfl_xor_sync(0xffffffffu, fs, o);
    }
    float invfs = 1.f / fs;
    *(float2*)&post[q * CPROT + 2 * lane] = make_float2(fx * invfs, fy * invfs);
    if (lane == 0) {
        float kf = klfr * (1.f / 64.f);
        float kr = klrf * (1.f / 64.f);
        g_klfr[q] = kf;
        g_klrf[q] = kr;
        sm5[0][warp] = (hr > hf && cr > cf) ? 1.f : 0.f;
        sm5[1][warp] = cr;
        sm5[2][warp] = cf;
        sm5[3][warp] = cf * kf;
        sm5[4][warp] = cr * kr;
    }
    __syncthreads();
    if (threadIdx.x < 5) {
        float s = 0.f;
        #pragma unroll
        for (int k = 0; k < 32; ++k) s += sm5[threadIdx.x][k];
        g_part[threadIdx.x][blockIdx.x] = s;
    }
}

// -------- kernel 4: finalize via warp shuffles --------
__global__ void __launch_bounds__(1024)
finalize_kernel(float* __restrict__ out) {
    __shared__ float s0[32], s1[32], s2[32];
    __shared__ int   sh_nr;
    __shared__ float sh_scr, sh_scf;
    const int t = threadIdx.x, lane = t & 31, warp = t >> 5;

    float v0 = g_part[0][2 * t] + g_part[0][2 * t + 1];
    float v1 = g_part[1][2 * t] + g_part[1][2 * t + 1];
    float v2 = g_part[2][2 * t] + g_part[2][2 * t + 1];
    #pragma unroll
    for (int o = 16; o; o >>= 1) {
        v0 += __shfl_xor_sync(0xffffffffu, v0, o);
        v1 += __shfl_xor_sync(0xffffffffu, v1, o);
        v2 += __shfl_xor_sync(0xffffffffu, v2, o);
    }
    if (lane == 0) { s0[warp] = v0; s1[warp] = v1; s2[warp] = v2; }
    __syncthreads();
    if (warp == 0) {
        v0 = s0[lane]; v1 = s1[lane]; v2 = s2[lane];
        #pragma unroll
        for (int o = 16; o; o >>= 1) {
            v0 += __shfl_xor_sync(0xffffffffu, v0, o);
            v1 += __shfl_xor_sync(0xffffffffu, v1, o);
            v2 += __shfl_xor_sync(0xffffffffu, v2, o);
        }
        if (lane == 0) { sh_nr = (int)v0; sh_scr = v1; sh_scf = v2; }
    }
    __syncthreads();

    const int nr = sh_nr, nf = Q_TOTAL - nr;
    const int fbA = nf >> 5, fbB = nr >> 5;

    const int b0 = 2 * t, b1 = 2 * t + 1;
    float sA = (b0 < fbA ? g_part[3][b0] : 0.f) + (b1 < fbA ? g_part[3][b1] : 0.f);
    float sB = (b0 < fbB ? g_part[4][b0] : 0.f) + (b1 < fbB ? g_part[4][b1] : 0.f);
    if (t < 32) {
        int iA = fbA * 32 + t;
        int iB = fbB * 32 + t;
        if (iA < nf) sA += g_c[1][iA] * g_klfr[iA];
        if (iB < nr) sB += g_c[0][iB] * g_klrf[iB];
    }
    #pragma unroll
    for (int o = 16; o; o >>= 1) {
        sA += __shfl_xor_sync(0xffffffffu, sA, o);
        sB += __shfl_xor_sync(0xffffffffu, sB, o);
    }
    if (lane == 0) { s0[warp] = sA; s1[warp] = sB; }
    __syncthreads();
    if (warp == 0) {
        sA = s0[lane]; sB = s1[lane];
        #pragma unroll
        for (int o = 16; o; o >>= 1) {
            sA += __shfl_xor_sync(0xffffffffu, sA, o);
            sB += __shfl_xor_sync(0xffffffffu, sB, o);
        }
        if (lane == 0) {
            out[0] = sA / sh_scf;   // L_f_r
            out[1] = sB / sh_scr;   // L_r_f
        }
    }
}

extern "C" void kernel_launch(void* const* d_in, const int* in_sizes, int n_in,
                              void* d_out, int out_size) {
    const float* ctx_r = (const float*)d_in[0];
    const float* ctx_f = (const float*)d_in[1];
    const float* tgt_r = (const float*)d_in[2];
    const float* tgt_f = (const float*)d_in[3];
    float* out = (float*)d_out;

    cudaFuncSetAttribute(posterior_mma, cudaFuncAttributeMaxDynamicSharedMemorySize,
                         SMEM_TOTAL);

    prep_kernel<<<2, 256>>>(ctx_r, ctx_f);
    posterior_mma<<<dim3(Q_TOTAL / QT, 2), 256, SMEM_TOTAL>>>(tgt_r, tgt_f, out);
    fuse_kernel<<<NPART, 1024>>>(out);
    finalize_kernel<<<1, 1024>>>(out);
}

// round 10
// speedup vs baseline: 1.2870x; 1.2870x over previous
#include <cuda_runtime.h>
#include <cuda_fp16.h>
#include <cstdint>

#define Q_TOTAL 65536
#define CPROT   64
#define DDIM    512
#define QT      128
#define KC      64                  // floats per K chunk
#define NCH     (DDIM / KC)         // 8
#define AST     144                 // bytes per smem row (128 data + 16 pad)

// ---- static smem layout (bytes) ----
#define OFF_AH   0
#define OFF_BH   (OFF_AH + QT * AST)        // 18432
#define OFF_SUMQ (OFF_BH + CPROT * AST)     // 27648 (128 floats)
#define OFF_SUMP (OFF_SUMQ + 512)           // 28160 (64 floats)
#define OFF_CMB  (OFF_SUMP + 256)           // 28416 (6*128 floats)
#define SMEM_TOTAL (OFF_CMB + 3072)         // 31488

#define NPART 2048

// -------- device scratch --------
__device__ float g_sump[2][CPROT];
__device__ uint4 g_ph4[2][4096];    // proto fp16: [mod][row*64 + unit], 8 fp16/unit
__device__ float g_c  [2][Q_TOTAL];
__device__ float g_h  [2][Q_TOTAL];
__device__ float g_S  [2][Q_TOTAL];
__device__ float g_klfr[Q_TOTAL];
__device__ float g_klrf[Q_TOTAL];
__device__ float g_part[5][NPART];

// -------- helpers --------
__device__ __forceinline__ uint32_t smem_u32(const void* p) {
    uint32_t a;
    asm("{ .reg .u64 t; cvta.to.shared.u64 t, %1; cvt.u32.u64 %0, t; }"
        : "=r"(a) : "l"(p));
    return a;
}

#define LDM4(r, a) \
    asm volatile("ldmatrix.sync.aligned.m8n8.x4.shared.b16 {%0,%1,%2,%3}, [%4];" \
        : "=r"((r)[0]), "=r"((r)[1]), "=r"((r)[2]), "=r"((r)[3]) : "r"(a))

__device__ __forceinline__ void mma16816(float* d, const uint32_t* a, const uint32_t* b) {
    asm volatile(
        "mma.sync.aligned.m16n8k16.row.col.f32.f16.f16.f32 "
        "{%0,%1,%2,%3}, {%4,%5,%6,%7}, {%8,%9}, {%0,%1,%2,%3};"
        : "+f"(d[0]), "+f"(d[1]), "+f"(d[2]), "+f"(d[3])
        : "r"(a[0]), "r"(a[1]), "r"(a[2]), "r"(a[3]), "r"(b[0]), "r"(b[1]));
}

__device__ __forceinline__ uint32_t h2pack(float x, float y) {
    __half2 h = __float22half2_rn(make_float2(x, y));
    return *reinterpret_cast<uint32_t*>(&h);
}

__device__ __forceinline__ float fast_sqrt(float x) {
    float xc = fmaxf(x, 1e-12f);
    return xc * rsqrtf(xc);
}

// -------- kernel 1: proto norms + proto fp16 precompute --------
__global__ void prep_kernel(const float* __restrict__ ctx_r,
                            const float* __restrict__ ctx_f) {
    const int mod = blockIdx.x;
    const float* ctx = mod ? ctx_f : ctx_r;
    const int tid = threadIdx.x;
    const int warp = tid >> 5, lane = tid & 31;

    for (int p = warp; p < CPROT; p += 8) {
        float s = 0.f;
        const float* row = ctx + (size_t)p * DDIM;
        for (int k = lane; k < DDIM; k += 32) { float v = row[k]; s += v * v; }
        #pragma unroll
        for (int o = 16; o; o >>= 1) s += __shfl_xor_sync(0xffffffffu, s, o);
        if (lane == 0) g_sump[mod][p] = s;
    }
    // fp16 convert: 4096 units of 8 floats
    for (int i = tid; i < 4096; i += 256) {
        const int row = i >> 6, u8 = i & 63;
        const float4 v0 = *(const float4*)(ctx + (size_t)row * DDIM + u8 * 8);
        const float4 v1 = *(const float4*)(ctx + (size_t)row * DDIM + u8 * 8 + 4);
        g_ph4[mod][i] = make_uint4(h2pack(v0.x, v0.y), h2pack(v0.z, v0.w),
                                   h2pack(v1.x, v1.y), h2pack(v1.z, v1.w));
    }
}

// -------- kernel 2: pipelined single-term fp16 mma posterior (R8 structure) --------
__global__ void __launch_bounds__(256, 2)
posterior_mma(const float* __restrict__ tgt_r, const float* __restrict__ tgt_f,
              float* __restrict__ out) {
    __shared__ __align__(16) char sm[SMEM_TOTAL];
    const int mod = blockIdx.y;
    const float* __restrict__ tgt = mod ? tgt_f : tgt_r;
    float* out_p = out + 2 + (mod ? (size_t)0 : (size_t)Q_TOTAL * CPROT);

    const int tid = threadIdx.x;
    const int l   = tid & 31;
    const int w   = tid >> 5;
    const int wq  = w & 3;          // 4 q-groups of 32 rows
    const int wp  = w >> 2;         // 2 p-groups of 32 cols
    const size_t qbase = (size_t)blockIdx.x * QT;

    const uint32_t sb = smem_u32(sm);
    float* sumq = (float*)(sm + OFF_SUMQ);
    float* sump = (float*)(sm + OFF_SUMP);
    float* cmb  = (float*)(sm + OFF_CMB);

    if (tid < CPROT) sump[tid] = g_sump[mod][tid];

    float d[2][4][4];
    #pragma unroll
    for (int mt = 0; mt < 2; ++mt)
        #pragma unroll
        for (int n = 0; n < 4; ++n)
            #pragma unroll
            for (int u = 0; u < 4; ++u) d[mt][n][u] = 0.f;

    float qn[8] = {0.f, 0.f, 0.f, 0.f, 0.f, 0.f, 0.f, 0.f};

    const uint32_t aoff = (uint32_t)((l & 15) * AST + (l >> 4) * 16);
    const uint32_t boff = (uint32_t)(((l & 7) + ((l >> 4) << 3)) * AST + (((l >> 3) & 1) * 16));
    uint32_t aHB[2], bHB[2];
    #pragma unroll
    for (int mt = 0; mt < 2; ++mt)
        aHB[mt] = sb + OFF_AH + (32 * wq + 16 * mt) * AST + aoff;
    #pragma unroll
    for (int np = 0; np < 2; ++np)
        bHB[np] = sb + OFF_BH + (32 * wp + 16 * np) * AST + boff;

    const int arow = tid >> 4;
    const int akq  = tid & 15;

    float4 va[8];
    #pragma unroll
    for (int i = 0; i < 8; ++i)
        va[i] = __ldcs((const float4*)(tgt + (qbase + 16 * i + arow) * DDIM + akq * 4));

    for (int c = 0; c < NCH; ++c) {
        const int kc = c * KC;
        __syncthreads();

        // ---- A: convert fp16 + store, |q|^2 in regs ----
        #pragma unroll
        for (int i = 0; i < 8; ++i) {
            const int row = 16 * i + arow;
            *(uint2*)(sm + OFF_AH + row * AST + akq * 8) =
                make_uint2(h2pack(va[i].x, va[i].y), h2pack(va[i].z, va[i].w));
            qn[i] += va[i].x * va[i].x + va[i].y * va[i].y
                   + va[i].z * va[i].z + va[i].w * va[i].w;
        }
        // ---- B: copy prepared fp16 (L2-hot) ----
        #pragma unroll
        for (int j = 0; j < 2; ++j) {
            const int g   = j * 256 + tid;
            const int row = g >> 3;
            const int u8  = g & 7;
            *(uint4*)(sm + OFF_BH + row * AST + u8 * 16) =
                g_ph4[mod][row * 64 + (kc >> 3) + u8];
        }
        __syncthreads();

        // ---- prefetch next chunk's A ----
        if (c + 1 < NCH) {
            #pragma unroll
            for (int i = 0; i < 8; ++i)
                va[i] = __ldcs((const float4*)(tgt + (qbase + 16 * i + arow) * DDIM
                                               + kc + KC + akq * 4));
        }

        // ---- compute: 4 k-steps of 16 ----
        #pragma unroll
        for (int ks = 0; ks < 4; ++ks) {
            const uint32_t ko = ks * 32;
            uint32_t ah[2][4], bh[2][4];
            #pragma unroll
            for (int mt = 0; mt < 2; ++mt) LDM4(ah[mt], aHB[mt] + ko);
            #pragma unroll
            for (int np = 0; np < 2; ++np) LDM4(bh[np], bHB[np] + ko);
            #pragma unroll
            for (int mt = 0; mt < 2; ++mt)
                #pragma unroll
                for (int n = 0; n < 4; ++n)
                    mma16816(d[mt][n], ah[mt], &bh[n >> 1][(n & 1) * 2]);
        }
    }

    #pragma unroll
    for (int i = 0; i < 8; ++i) {
        float s = qn[i];
        s += __shfl_xor_sync(0xffffffffu, s, 1);
        s += __shfl_xor_sync(0xffffffffu, s, 2);
        s += __shfl_xor_sync(0xffffffffu, s, 4);
        s += __shfl_xor_sync(0xffffffffu, s, 8);
        if ((tid & 15) == 0) sumq[16 * i + arow] = s;
    }
    __syncthreads();

    // ---- epilogue pass 1: per-warp 32-col partials ----
    const int qr    = l >> 2;
    const int cbase = (l & 3) * 2;
    float sp[4][2];
    #pragma unroll
    for (int n = 0; n < 4; ++n) {
        sp[n][0] = sump[32 * wp + 8 * n + cbase];
        sp[n][1] = sump[32 * wp + 8 * n + cbase + 1];
    }

    #pragma unroll
    for (int mt = 0; mt < 2; ++mt)
        #pragma unroll
        for (int h = 0; h < 2; ++h) {
            const int r = 32 * wq + 16 * mt + 8 * h + qr;
            const float sq = sumq[r];
            float S = 0.f, T = 0.f, emax = 0.f;
            #pragma unroll
            for (int n = 0; n < 4; ++n) {
                float dist0 = fast_sqrt(sq - 2.f * d[mt][n][2 * h]     + sp[n][0]);
                float dist1 = fast_sqrt(sq - 2.f * d[mt][n][2 * h + 1] + sp[n][1]);
                float e0 = __expf(-dist0), e1 = __expf(-dist1);
                d[mt][n][2 * h]     = e0;
                d[mt][n][2 * h + 1] = e1;
                S += e0 + e1;
                T += e0 * dist0 + e1 * dist1;
                emax = fmaxf(emax, fmaxf(e0, e1));
            }
            #pragma unroll
            for (int o = 1; o < 4; o <<= 1) {
                S += __shfl_xor_sync(0xffffffffu, S, o);
                T += __shfl_xor_sync(0xffffffffu, T, o);
                emax = fmaxf(emax, __shfl_xor_sync(0xffffffffu, emax, o));
            }
            if ((l & 3) == 0) {
                cmb[wp * 128 + r]       = S;
                cmb[256 + wp * 128 + r] = T;
                cmb[512 + wp * 128 + r] = emax;
            }
        }
    __syncthreads();

    // ---- epilogue pass 2: combine 2 col-groups, write outputs ----
    #pragma unroll
    for (int mt = 0; mt < 2; ++mt)
        #pragma unroll
        for (int h = 0; h < 2; ++h) {
            const int r = 32 * wq + 16 * mt + 8 * h + qr;
            const float S = cmb[r] + cmb[128 + r];
            const float T = cmb[256 + r] + cmb[384 + r];
            const float M = fmaxf(cmb[512 + r], cmb[640 + r]);
            const float invS = 1.f / S;
            const size_t qg = qbase + r;
            float* orow = &out_p[qg * CPROT + 32 * wp];
            #pragma unroll
            for (int n = 0; n < 4; ++n)
                *(float2*)&orow[8 * n + cbase] =
                    make_float2(d[mt][n][2 * h] * invS, d[mt][n][2 * h + 1] * invS);
            if (wp == 0 && (l & 3) == 0) {
                g_c[mod][qg] = M * invS;
                g_S[mod][qg] = S;
                g_h[mod][qg] = __logf(S) + T * invS;
            }
        }
}

// -------- kernel 3: AMI fuse + per-query KL + block partials --------
__global__ void __launch_bounds__(1024)
fuse_kernel(float* __restrict__ out) {
    __shared__ float sm5[5][32];
    const int warp = threadIdx.x >> 5, lane = threadIdx.x & 31;
    const size_t q = (size_t)blockIdx.x * 32 + warp;
    const float* p_f = out + 2;
    const float* p_r = out + 2 + (size_t)Q_TOTAL * CPROT;
    float* post      = out + 2 + 2 * (size_t)Q_TOTAL * CPROT;

    float2 pf = *(const float2*)&p_f[q * CPROT + 2 * lane];
    float2 pr = *(const float2*)&p_r[q * CPROT + 2 * lane];
    float cr = g_c[0][q], cf = g_c[1][q];
    float Sr = g_S[0][q], Sf = g_S[1][q];
    float hr = g_h[0][q], hf = g_h[1][q];

    float klfr = pf.x * (__logf(pf.x) - pr.x) + pf.y * (__logf(pf.y) - pr.y);
    float klrf = pr.x * (__logf(pr.x) - pf.x) + pr.y * (__logf(pr.y) - pf.y);

    float inv = 1.f / (cr + cf);
    float a = cr * inv * Sr;
    float b = cf * inv * Sf;
    float fx = a * pr.x + b * pf.x;
    float fy = a * pr.y + b * pf.y;
    float fs = fx + fy;

    #pragma unroll
    for (int o = 1; o < 32; o <<= 1) {
        klfr += __shfl_xor_sync(0xffffffffu, klfr, o);
        klrf += __shfl_xor_sync(0xffffffffu, klrf, o);
        fs   += __shfl_xor_sync(0xffffffffu, fs, o);
    }
    float invfs = 1.f / fs;
    *(float2*)&post[q * CPROT + 2 * lane] = make_float2(fx * invfs, fy * invfs);
    if (lane == 0) {
        float kf = klfr * (1.f / 64.f);
        float kr = klrf * (1.f / 64.f);
        g_klfr[q] = kf;
        g_klrf[q] = kr;
        sm5[0][warp] = (hr > hf && cr > cf) ? 1.f : 0.f;
        sm5[1][warp] = cr;
        sm5[2][warp] = cf;
        sm5[3][warp] = cf * kf;
        sm5[4][warp] = cr * kr;
    }
    __syncthreads();
    if (threadIdx.x < 5) {
        float s = 0.f;
        #pragma unroll
        for (int k = 0; k < 32; ++k) s += sm5[threadIdx.x][k];
        g_part[threadIdx.x][blockIdx.x] = s;
    }
}

// -------- kernel 4: finalize via warp shuffles --------
__global__ void __launch_bounds__(1024)
finalize_kernel(float* __restrict__ out) {
    __shared__ float s0[32], s1[32], s2[32];
    __shared__ int   sh_nr;
    __shared__ float sh_scr, sh_scf;
    const int t = threadIdx.x, lane = t & 31, warp = t >> 5;

    float v0 = g_part[0][2 * t] + g_part[0][2 * t + 1];
    float v1 = g_part[1][2 * t] + g_part[1][2 * t + 1];
    float v2 = g_part[2][2 * t] + g_part[2][2 * t + 1];
    #pragma unroll
    for (int o = 16; o; o >>= 1) {
        v0 += __shfl_xor_sync(0xffffffffu, v0, o);
        v1 += __shfl_xor_sync(0xffffffffu, v1, o);
        v2 += __shfl_xor_sync(0xffffffffu, v2, o);
    }
    if (lane == 0) { s0[warp] = v0; s1[warp] = v1; s2[warp] = v2; }
    __syncthreads();
    if (warp == 0) {
        v0 = s0[lane]; v1 = s1[lane]; v2 = s2[lane];
        #pragma unroll
        for (int o = 16; o; o >>= 1) {
            v0 += __shfl_xor_sync(0xffffffffu, v0, o);
            v1 += __shfl_xor_sync(0xffffffffu, v1, o);
            v2 += __shfl_xor_sync(0xffffffffu, v2, o);
        }
        if (lane == 0) { sh_nr = (int)v0; sh_scr = v1; sh_scf = v2; }
    }
    __syncthreads();

    const int nr = sh_nr, nf = Q_TOTAL - nr;
    const int fbA = nf >> 5, fbB = nr >> 5;

    const int b0 = 2 * t, b1 = 2 * t + 1;
    float sA = (b0 < fbA ? g_part[3][b0] : 0.f) + (b1 < fbA ? g_part[3][b1] : 0.f);
    float sB = (b0 < fbB ? g_part[4][b0] : 0.f) + (b1 < fbB ? g_part[4][b1] : 0.f);
    if (t < 32) {
        int iA = fbA * 32 + t;
        int iB = fbB * 32 + t;
        if (iA < nf) sA += g_c[1][iA] * g_klfr[iA];
        if (iB < nr) sB += g_c[0][iB] * g_klrf[iB];
    }
    #pragma unroll
    for (int o = 16; o; o >>= 1) {
        sA += __shfl_xor_sync(0xffffffffu, sA, o);
        sB += __shfl_xor_sync(0xffffffffu, sB, o);
    }
    if (lane == 0) { s0[warp] = sA; s1[warp] = sB; }
    __syncthreads();
    if (warp == 0) {
        sA = s0[lane]; sB = s1[lane];
        #pragma unroll
        for (int o = 16; o; o >>= 1) {
            sA += __shfl_xor_sync(0xffffffffu, sA, o);
            sB += __shfl_xor_sync(0xffffffffu, sB, o);
        }
        if (lane == 0) {
            out[0] = sA / sh_scf;   // L_f_r
            out[1] = sB / sh_scr;   // L_r_f
        }
    }
}

extern "C" void kernel_launch(void* const* d_in, const int* in_sizes, int n_in,
                              void* d_out, int out_size) {
    const float* ctx_r = (const float*)d_in[0];
    const float* ctx_f = (const float*)d_in[1];
    const float* tgt_r = (const float*)d_in[2];
    const float* tgt_f = (const float*)d_in[3];
    float* out = (float*)d_out;

    prep_kernel<<<2, 256>>>(ctx_r, ctx_f);
    posterior_mma<<<dim3(Q_TOTAL / QT, 2), 256>>>(tgt_r, tgt_f, out);
    fuse_kernel<<<NPART, 1024>>>(out);
    finalize_kernel<<<1, 1024>>>(out);
}